// round 2
// baseline (speedup 1.0000x reference)
#include <cuda_runtime.h>

// Problem constants
#define BATCH   8
#define T_SEQ   512
#define DMODEL  1024
#define NH      16
#define DK      64
#define S_REL   1023          // 2T-1
#define BT      (BATCH*T_SEQ) // 4096
#define THREE_D (3*DMODEL)    // 3072

// Scratch (device globals; no allocation allowed)
__device__ float g_qkv[BT * THREE_D];   // [B,T, 3D]  (q | k | v per row)
__device__ float g_p[S_REL * DMODEL];   // [S, D] positional projection
__device__ float g_ctx[BT * DMODEL];    // [B,T,D] attention context

// ---------------------------------------------------------------------------
// SGEMM (NT): C[M,N] = A[M,K] @ B[N,K]^T + bias[N]
// 128x128 tile, BK=8, 256 threads, 8x8 per thread.
// ---------------------------------------------------------------------------
__global__ __launch_bounds__(256, 2)
void sgemm_nt(const float* __restrict__ A, const float* __restrict__ Bm,
              const float* __restrict__ bias, float* __restrict__ C,
              int M, int N, int K)
{
    __shared__ __align__(16) float As[8][128];
    __shared__ __align__(16) float Bs[8][128];

    const int tid  = threadIdx.x;
    const int m0   = blockIdx.y * 128;
    const int n0   = blockIdx.x * 128;
    const int tx   = tid & 15;
    const int ty   = tid >> 4;
    const int lrow = tid >> 1;          // 0..127
    const int lcol = (tid & 1) * 4;     // 0 or 4

    float acc[8][8];
#pragma unroll
    for (int i = 0; i < 8; i++)
#pragma unroll
        for (int j = 0; j < 8; j++) acc[i][j] = 0.f;

    for (int k0 = 0; k0 < K; k0 += 8) {
        float4 av = make_float4(0.f, 0.f, 0.f, 0.f);
        if (m0 + lrow < M)
            av = *(const float4*)(A + (size_t)(m0 + lrow) * K + k0 + lcol);
        float4 bv = make_float4(0.f, 0.f, 0.f, 0.f);
        if (n0 + lrow < N)
            bv = *(const float4*)(Bm + (size_t)(n0 + lrow) * K + k0 + lcol);
        As[lcol + 0][lrow] = av.x; As[lcol + 1][lrow] = av.y;
        As[lcol + 2][lrow] = av.z; As[lcol + 3][lrow] = av.w;
        Bs[lcol + 0][lrow] = bv.x; Bs[lcol + 1][lrow] = bv.y;
        Bs[lcol + 2][lrow] = bv.z; Bs[lcol + 3][lrow] = bv.w;
        __syncthreads();
#pragma unroll
        for (int k = 0; k < 8; k++) {
            float a[8], b[8];
            *(float4*)(a)     = *(const float4*)&As[k][ty * 8];
            *(float4*)(a + 4) = *(const float4*)&As[k][ty * 8 + 4];
            *(float4*)(b)     = *(const float4*)&Bs[k][tx * 8];
            *(float4*)(b + 4) = *(const float4*)&Bs[k][tx * 8 + 4];
#pragma unroll
            for (int i = 0; i < 8; i++)
#pragma unroll
                for (int j = 0; j < 8; j++)
                    acc[i][j] += a[i] * b[j];
        }
        __syncthreads();
    }

#pragma unroll
    for (int i = 0; i < 8; i++) {
        int row = m0 + ty * 8 + i;
        if (row < M) {
#pragma unroll
            for (int j = 0; j < 8; j += 4) {
                int col = n0 + tx * 8 + j;
                float4 v;
                v.x = acc[i][j + 0] + (bias ? bias[col + 0] : 0.f);
                v.y = acc[i][j + 1] + (bias ? bias[col + 1] : 0.f);
                v.z = acc[i][j + 2] + (bias ? bias[col + 2] : 0.f);
                v.w = acc[i][j + 3] + (bias ? bias[col + 3] : 0.f);
                *(float4*)(C + (size_t)row * N + col) = v;
            }
        }
    }
}

// ---------------------------------------------------------------------------
// Attention: per block = (b, h, 32 query rows).
//   AC[t,s]  = (q[t]+posu) . k[s]        (4 s-tiles of 128)
//   BD via diagonal GEMM: C2[t,j] = (q[t]+posv) . p[j+511], scatter to s=t+j
// Then scale, mask, softmax, write weights.
// Dynamic smem: qu(32x65) + qv(32x65) + buf(128x65) + scores(32x512)
// ---------------------------------------------------------------------------
#define ATTN_SMEM ((32*65*2 + 128*65 + 32*512) * 4)   // 115456 bytes

__global__ __launch_bounds__(256, 1)
void attn_kernel(const float* __restrict__ posu, const float* __restrict__ posv,
                 const int* __restrict__ mask,
                 float* __restrict__ weights)
{
    const int bid   = blockIdx.x;          // 2048 blocks
    const int ttile = bid & 15;
    const int h     = (bid >> 4) & 15;
    const int b     = bid >> 8;
    const int t0    = ttile * 32;

    extern __shared__ float sm[];
    float* qu  = sm;                 // 32 x 65
    float* qv  = qu + 32 * 65;       // 32 x 65
    float* buf = qv + 32 * 65;       // 128 x 65
    float* sc  = buf + 128 * 65;     // 32 x 512

    const int tid = threadIdx.x;
    const int tx  = tid & 31;
    const int ty  = tid >> 5;

    // load q tile, add posu/posv
#pragma unroll
    for (int i = 0; i < 8; i++) {
        int e  = i * 256 + tid;       // 0..2047
        int tt = e >> 6;
        int d  = e & 63;
        float qval = g_qkv[(size_t)(b * T_SEQ + t0 + tt) * THREE_D + h * DK + d];
        qu[tt * 65 + d] = qval + posu[h * DK + d];
        qv[tt * 65 + d] = qval + posv[h * DK + d];
    }
    __syncthreads();

    // ---------------- AC pass: scores[t][s] = qu[t].k[s] ----------------
    for (int st = 0; st < 4; st++) {
        const int s0 = st * 128;
#pragma unroll
        for (int i = 0; i < 32; i++) {
            int e  = i * 256 + tid;
            int ss = e >> 6;
            int d  = e & 63;
            buf[ss * 65 + d] =
                g_qkv[(size_t)(b * T_SEQ + s0 + ss) * THREE_D + DMODEL + h * DK + d];
        }
        __syncthreads();

        float acc[4][4];
#pragma unroll
        for (int i = 0; i < 4; i++)
#pragma unroll
            for (int j = 0; j < 4; j++) acc[i][j] = 0.f;

#pragma unroll 8
        for (int d = 0; d < 64; d++) {
            float a0 = qu[(ty * 4 + 0) * 65 + d];
            float a1 = qu[(ty * 4 + 1) * 65 + d];
            float a2 = qu[(ty * 4 + 2) * 65 + d];
            float a3 = qu[(ty * 4 + 3) * 65 + d];
            float b0 = buf[(tx      ) * 65 + d];
            float b1 = buf[(tx +  32) * 65 + d];
            float b2 = buf[(tx +  64) * 65 + d];
            float b3 = buf[(tx +  96) * 65 + d];
            acc[0][0] += a0 * b0; acc[0][1] += a0 * b1; acc[0][2] += a0 * b2; acc[0][3] += a0 * b3;
            acc[1][0] += a1 * b0; acc[1][1] += a1 * b1; acc[1][2] += a1 * b2; acc[1][3] += a1 * b3;
            acc[2][0] += a2 * b0; acc[2][1] += a2 * b1; acc[2][2] += a2 * b2; acc[2][3] += a2 * b3;
            acc[3][0] += a3 * b0; acc[3][1] += a3 * b1; acc[3][2] += a3 * b2; acc[3][3] += a3 * b3;
        }
#pragma unroll
        for (int i = 0; i < 4; i++)
#pragma unroll
            for (int j = 0; j < 4; j++)
                sc[(ty * 4 + i) * 512 + s0 + tx + j * 32] = acc[i][j];
        __syncthreads();
    }

    // ---------------- BD pass (diagonal): c[t,j] = qv[t].p[j+511] --------
    const int jlo = -(t0 + 31);
    for (int jt = 0; jt < 5; jt++) {
        const int j0 = jlo + jt * 128;
#pragma unroll
        for (int i = 0; i < 32; i++) {
            int e = i * 256 + tid;
            int r = e >> 6;
            int d = e & 63;
            int prow = j0 + r + (T_SEQ - 1);
            buf[r * 65 + d] = (prow >= 0 && prow < S_REL)
                ? g_p[(size_t)prow * DMODEL + h * DK + d] : 0.f;
        }
        __syncthreads();

        float acc[4][4];
#pragma unroll
        for (int i = 0; i < 4; i++)
#pragma unroll
            for (int j = 0; j < 4; j++) acc[i][j] = 0.f;

#pragma unroll 8
        for (int d = 0; d < 64; d++) {
            float a0 = qv[(ty * 4 + 0) * 65 + d];
            float a1 = qv[(ty * 4 + 1) * 65 + d];
            float a2 = qv[(ty * 4 + 2) * 65 + d];
            float a3 = qv[(ty * 4 + 3) * 65 + d];
            float b0 = buf[(tx      ) * 65 + d];
            float b1 = buf[(tx +  32) * 65 + d];
            float b2 = buf[(tx +  64) * 65 + d];
            float b3 = buf[(tx +  96) * 65 + d];
            acc[0][0] += a0 * b0; acc[0][1] += a0 * b1; acc[0][2] += a0 * b2; acc[0][3] += a0 * b3;
            acc[1][0] += a1 * b0; acc[1][1] += a1 * b1; acc[1][2] += a1 * b2; acc[1][3] += a1 * b3;
            acc[2][0] += a2 * b0; acc[2][1] += a2 * b1; acc[2][2] += a2 * b2; acc[2][3] += a2 * b3;
            acc[3][0] += a3 * b0; acc[3][1] += a3 * b1; acc[3][2] += a3 * b2; acc[3][3] += a3 * b3;
        }
#pragma unroll
        for (int i = 0; i < 4; i++) {
            int tt = ty * 4 + i;
#pragma unroll
            for (int j = 0; j < 4; j++) {
                int jglob = j0 + tx + j * 32;
                int s = t0 + tt + jglob;          // global key index
                if (s >= 0 && s < T_SEQ)
                    sc[tt * 512 + s] += acc[i][j];
            }
        }
        __syncthreads();
    }

    // ---------------- scale + mask + softmax + write weights -------------
    const int wid  = tid >> 5;
    const int lane = tid & 31;
#pragma unroll
    for (int rr = 0; rr < 4; rr++) {
        const int tt = wid * 4 + rr;
        const int t  = t0 + tt;
        const int* mrow = mask + ((size_t)b * T_SEQ + t) * T_SEQ;

        float mx = -3.4e38f;
        for (int c = lane; c < T_SEQ; c += 32) {
            float v = sc[tt * 512 + c] * 0.125f;       // 1/sqrt(64)
            v = mrow[c] ? v : -100000.0f;
            sc[tt * 512 + c] = v;
            mx = fmaxf(mx, v);
        }
#pragma unroll
        for (int off = 16; off > 0; off >>= 1)
            mx = fmaxf(mx, __shfl_xor_sync(0xffffffffu, mx, off));

        float sum = 0.f;
        for (int c = lane; c < T_SEQ; c += 32) {
            float e = __expf(sc[tt * 512 + c] - mx);
            sc[tt * 512 + c] = e;
            sum += e;
        }
#pragma unroll
        for (int off = 16; off > 0; off >>= 1)
            sum += __shfl_xor_sync(0xffffffffu, sum, off);
        float inv = 1.f / sum;

        float* wrow = weights + (((size_t)b * NH + h) * T_SEQ + t) * T_SEQ;
        for (int c = lane; c < T_SEQ; c += 32)
            wrow[c] = sc[tt * 512 + c] * inv;
    }
}

// ---------------------------------------------------------------------------
// ctx[b,t,h,:] = sum_s weights[b,h,t,s] * v[b,s,h,:]
// block = (b, h, 64 t-rows); 256 threads, 4x4 per thread; K-tiles of 64.
// ---------------------------------------------------------------------------
__global__ __launch_bounds__(256, 2)
void ctx_kernel(const float* __restrict__ weights)
{
    const int bid   = blockIdx.x;          // 1024 blocks
    const int ttile = bid & 7;
    const int h     = (bid >> 3) & 15;
    const int b     = bid >> 7;
    const int t0    = ttile * 64;

    __shared__ float ws[64][65];
    __shared__ float vs[64][65];

    const int tid = threadIdx.x;
    const int tx  = tid & 15;
    const int ty  = tid >> 4;

    float acc[4][4];
#pragma unroll
    for (int i = 0; i < 4; i++)
#pragma unroll
        for (int j = 0; j < 4; j++) acc[i][j] = 0.f;

    const float* wbase = weights + (((size_t)b * NH + h) * T_SEQ + t0) * T_SEQ;

    for (int s0 = 0; s0 < T_SEQ; s0 += 64) {
#pragma unroll
        for (int i = 0; i < 16; i++) {
            int e = i * 256 + tid;
            int r = e >> 6;
            int c = e & 63;
            ws[r][c] = wbase[(size_t)r * T_SEQ + s0 + c];
        }
#pragma unroll
        for (int i = 0; i < 16; i++) {
            int e = i * 256 + tid;
            int r = e >> 6;
            int c = e & 63;
            vs[r][c] = g_qkv[(size_t)(b * T_SEQ + s0 + r) * THREE_D + 2 * DMODEL + h * DK + c];
        }
        __syncthreads();
#pragma unroll 8
        for (int s = 0; s < 64; s++) {
            float a0 = ws[ty * 4 + 0][s];
            float a1 = ws[ty * 4 + 1][s];
            float a2 = ws[ty * 4 + 2][s];
            float a3 = ws[ty * 4 + 3][s];
            float b0 = vs[s][tx     ];
            float b1 = vs[s][tx + 16];
            float b2 = vs[s][tx + 32];
            float b3 = vs[s][tx + 48];
            acc[0][0] += a0 * b0; acc[0][1] += a0 * b1; acc[0][2] += a0 * b2; acc[0][3] += a0 * b3;
            acc[1][0] += a1 * b0; acc[1][1] += a1 * b1; acc[1][2] += a1 * b2; acc[1][3] += a1 * b3;
            acc[2][0] += a2 * b0; acc[2][1] += a2 * b1; acc[2][2] += a2 * b2; acc[2][3] += a2 * b3;
            acc[3][0] += a3 * b0; acc[3][1] += a3 * b1; acc[3][2] += a3 * b2; acc[3][3] += a3 * b3;
        }
        __syncthreads();
    }
#pragma unroll
    for (int i = 0; i < 4; i++) {
        int t = t0 + ty * 4 + i;
#pragma unroll
        for (int j = 0; j < 4; j++) {
            int d = tx + j * 16;
            g_ctx[(size_t)(b * T_SEQ + t) * DMODEL + h * DK + d] = acc[i][j];
        }
    }
}

// ---------------------------------------------------------------------------
extern "C" void kernel_launch(void* const* d_in, const int* in_sizes, int n_in,
                              void* d_out, int out_size)
{
    const float* x    = (const float*)d_in[0];
    const int*   mask = (const int*)d_in[1];
    const float* pos  = (const float*)d_in[2];
    const float* Wqkv = (const float*)d_in[3];
    const float* bqkv = (const float*)d_in[4];
    const float* Wpos = (const float*)d_in[5];
    const float* posu = (const float*)d_in[6];
    const float* posv = (const float*)d_in[7];
    const float* Wout = (const float*)d_in[8];
    const float* bout = (const float*)d_in[9];

    float* out     = (float*)d_out;
    float* weights = out + (size_t)BT * DMODEL;   // tuple: (out, weights)

    float* qkv_buf; cudaGetSymbolAddress((void**)&qkv_buf, g_qkv);
    float* p_buf;   cudaGetSymbolAddress((void**)&p_buf,   g_p);
    float* ctx_buf; cudaGetSymbolAddress((void**)&ctx_buf, g_ctx);

    // 1) QKV projection: [4096,3072] = x[4096,1024] @ Wqkv[3072,1024]^T + bqkv
    {
        dim3 grid(THREE_D / 128, BT / 128);
        sgemm_nt<<<grid, 256>>>(x, Wqkv, bqkv, qkv_buf, BT, THREE_D, DMODEL);
    }
    // 2) positional projection: [1023,1024] = pos @ Wpos^T (no bias)
    {
        dim3 grid(DMODEL / 128, (S_REL + 127) / 128);
        sgemm_nt<<<grid, 256>>>(pos, Wpos, nullptr, p_buf, S_REL, DMODEL, DMODEL);
    }
    // 3) attention scores + softmax -> weights
    {
        cudaFuncSetAttribute(attn_kernel,
                             cudaFuncAttributeMaxDynamicSharedMemorySize, ATTN_SMEM);
        attn_kernel<<<BATCH * NH * (T_SEQ / 32), 256, ATTN_SMEM>>>(posu, posv, mask, weights);
    }
    // 4) ctx = weights @ v
    {
        ctx_kernel<<<BATCH * NH * (T_SEQ / 64), 256>>>(weights);
    }
    // 5) out = ctx @ Wout^T + bout
    {
        dim3 grid(DMODEL / 128, BT / 128);
        sgemm_nt<<<grid, 256>>>(ctx_buf, Wout, bout, out, BT, DMODEL, DMODEL);
    }
}